// round 2
// baseline (speedup 1.0000x reference)
#include <cuda_runtime.h>
#include <math.h>

// Problem constants
#define NN   50000
#define EE   800000
#define E2V  (EE + NN)     // edges + self loops = 850000
#define F1   256           // heads * hid = 8*32
#define OUTC 40

// Scratch (device globals: allocation-free rule)
__device__ float g_h   [(size_t)NN * F1];   // per-layer transformed features h = x@W
__device__ float g_out [(size_t)NN * F1];   // aggregated output / next layer's x
__device__ float g_asrc[NN * 8];
__device__ float g_adst[NN * 8];
__device__ float g_max [NN * 8];
__device__ float g_sum [NN * 8];

// ---------------------------------------------------------------------------
// SGEMM: C(g_h) = A[M,K] @ B[K,Ncol], fp32, 128x64x16 tiles, 256 thr, 8x4/thr
// ---------------------------------------------------------------------------
#define BM 128
#define BN 64
#define BK 16
#define TM 8
#define TN 4

__global__ void sgemm_k(const float* __restrict__ Aext, const float* __restrict__ B,
                        int M, int Ncol, int K, int a_internal)
{
    const float* A = a_internal ? g_out : Aext;
    __shared__ float As[BK][BM + 4];
    __shared__ float Bs[BK][BN];
    int bm = blockIdx.y * BM;
    int bn = blockIdx.x * BN;
    int tid = threadIdx.x;
    int tx = tid & 15;
    int ty = tid >> 4;
    float acc[TM][TN];
    #pragma unroll
    for (int i = 0; i < TM; i++)
        #pragma unroll
        for (int j = 0; j < TN; j++) acc[i][j] = 0.f;

    for (int k0 = 0; k0 < K; k0 += BK) {
        #pragma unroll
        for (int i = 0; i < (BM * BK) / 256; i++) {
            int idx = tid + i * 256;
            int r = idx >> 4;      // /16
            int c = idx & 15;
            int gr = bm + r;
            As[c][r] = (gr < M) ? A[(size_t)gr * K + k0 + c] : 0.f;
        }
        #pragma unroll
        for (int i = 0; i < (BK * BN) / 256; i++) {
            int idx = tid + i * 256;
            int r = idx >> 6;      // /64
            int c = idx & 63;
            int gc = bn + c;
            Bs[r][c] = (gc < Ncol) ? B[(size_t)(k0 + r) * Ncol + gc] : 0.f;
        }
        __syncthreads();
        #pragma unroll
        for (int k = 0; k < BK; k++) {
            float ra[TM], rb[TN];
            #pragma unroll
            for (int i = 0; i < TM; i++) ra[i] = As[k][ty * TM + i];
            #pragma unroll
            for (int j = 0; j < TN; j++) rb[j] = Bs[k][tx * TN + j];
            #pragma unroll
            for (int i = 0; i < TM; i++)
                #pragma unroll
                for (int j = 0; j < TN; j++)
                    acc[i][j] = fmaf(ra[i], rb[j], acc[i][j]);
        }
        __syncthreads();
    }
    #pragma unroll
    for (int i = 0; i < TM; i++) {
        int r = bm + ty * TM + i;
        if (r >= M) continue;
        #pragma unroll
        for (int j = 0; j < TN; j++) {
            int c = bn + tx * TN + j;
            if (c < Ncol) g_h[(size_t)r * Ncol + c] = acc[i][j];
        }
    }
}

// ---------------------------------------------------------------------------
// Per-(node, head) attention dot products + init max/sum
// ---------------------------------------------------------------------------
__global__ void dots_k(const float* __restrict__ att_s, const float* __restrict__ att_d,
                       int N, int H, int C)
{
    int i = blockIdx.x * blockDim.x + threadIdx.x;
    if (i >= N * H) return;
    int n = i / H, hh = i % H;
    const float* hp = g_h + (size_t)n * H * C + hh * C;
    const float* as = att_s + hh * C;
    const float* ad = att_d + hh * C;
    float s = 0.f, d = 0.f;
    for (int c = 0; c < C; c++) {
        float v = hp[c];
        s = fmaf(v, as[c], s);
        d = fmaf(v, ad[c], d);
    }
    g_asrc[i] = s;
    g_adst[i] = d;
    g_max[i]  = __int_as_float(0xFF800000);  // -inf
    g_sum[i]  = 0.f;
}

// ---------------------------------------------------------------------------
// Float atomic max: sign-aware signed-max / unsigned-min trick (order-free)
// ---------------------------------------------------------------------------
__device__ __forceinline__ void atomicMaxF(float* addr, float val)
{
    unsigned int u = __float_as_uint(val);
    if (u >> 31) atomicMin((unsigned int*)addr, u);
    else         atomicMax((int*)addr, (int)u);
}

template<int H>
__global__ void edge_max_k(const int* __restrict__ src, const int* __restrict__ dst)
{
    int i = blockIdx.x * blockDim.x + threadIdx.x;
    if (i >= E2V * H) return;
    int e = i / H, hh = i % H;
    int s, d;
    if (e < EE) { s = src[e]; d = dst[e]; } else { s = d = e - EE; }
    float v = g_asrc[s * H + hh] + g_adst[d * H + hh];
    v = v > 0.f ? v : 0.2f * v;
    atomicMaxF(&g_max[d * H + hh], v);
}

template<int H>
__global__ void edge_sum_k(const int* __restrict__ src, const int* __restrict__ dst)
{
    int i = blockIdx.x * blockDim.x + threadIdx.x;
    if (i >= E2V * H) return;
    int e = i / H, hh = i % H;
    int s, d;
    if (e < EE) { s = src[e]; d = dst[e]; } else { s = d = e - EE; }
    float v = g_asrc[s * H + hh] + g_adst[d * H + hh];
    v = v > 0.f ? v : 0.2f * v;
    float ex = __expf(v - g_max[d * H + hh]);
    atomicAdd(&g_sum[d * H + hh], ex);
}

// ---------------------------------------------------------------------------
// Aggregation: warp per edge; lanes 0-7 compute the 8 head alphas, shuffle,
// then 8 coalesced 128B segments of h[src] scaled and atomicAdd'ed to out[dst]
// ---------------------------------------------------------------------------
__global__ void aggregate8_k(const int* __restrict__ src, const int* __restrict__ dst)
{
    int g = blockIdx.x * blockDim.x + threadIdx.x;
    int w = g >> 5;
    int lane = g & 31;
    if (w >= E2V) return;
    int s, d;
    if (w < EE) { s = src[w]; d = dst[w]; } else { s = d = w - EE; }
    float alpha = 0.f;
    if (lane < 8) {
        float v = g_asrc[s * 8 + lane] + g_adst[d * 8 + lane];
        v = v > 0.f ? v : 0.2f * v;
        alpha = __expf(v - g_max[d * 8 + lane]) / (g_sum[d * 8 + lane] + 1e-16f);
    }
    const float* hp = g_h + (size_t)s * F1;
    float* op = g_out + (size_t)d * F1;
    #pragma unroll
    for (int hh = 0; hh < 8; hh++) {
        float a = __shfl_sync(0xffffffffu, alpha, hh);
        atomicAdd(&op[hh * 32 + lane], hp[hh * 32 + lane] * a);
    }
}

__global__ void aggregate1_k(const int* __restrict__ src, const int* __restrict__ dst)
{
    int g = blockIdx.x * blockDim.x + threadIdx.x;
    int w = g >> 5;
    int lane = g & 31;
    if (w >= E2V) return;
    int s, d;
    if (w < EE) { s = src[w]; d = dst[w]; } else { s = d = w - EE; }
    float alpha = 0.f;
    if (lane == 0) {
        float v = g_asrc[s] + g_adst[d];
        v = v > 0.f ? v : 0.2f * v;
        alpha = __expf(v - g_max[d]) / (g_sum[d] + 1e-16f);
    }
    alpha = __shfl_sync(0xffffffffu, alpha, 0);
    const float* hp = g_h + (size_t)s * OUTC;
    float* op = g_out + (size_t)d * OUTC;
    for (int c = lane; c < OUTC; c += 32)
        atomicAdd(&op[c], hp[c] * alpha);
}

// ---------------------------------------------------------------------------
// Elementwise helpers
// ---------------------------------------------------------------------------
__global__ void zero_out_k(int total)
{
    int i = blockIdx.x * blockDim.x + threadIdx.x;
    if (i < total) g_out[i] = 0.f;
}

__global__ void bias_relu_k(const float* __restrict__ bias, int total)
{
    int i = blockIdx.x * blockDim.x + threadIdx.x;
    if (i >= total) return;
    float v = g_out[i] + bias[i & (F1 - 1)];
    g_out[i] = v > 0.f ? v : 0.f;
}

// Final: out = log_softmax(g_out + b3), warp per node (40 cols -> 2/lane)
__global__ void logsoftmax_k(const float* __restrict__ bias, float* __restrict__ out)
{
    int g = blockIdx.x * blockDim.x + threadIdx.x;
    int w = g >> 5;
    int lane = g & 31;
    if (w >= NN) return;
    const float* ip = g_out + (size_t)w * OUTC;
    float v0 = (lane < OUTC)      ? ip[lane] + bias[lane]           : -INFINITY;
    float v1 = (lane + 32 < OUTC) ? ip[lane + 32] + bias[lane + 32] : -INFINITY;
    float m = fmaxf(v0, v1);
    #pragma unroll
    for (int o = 16; o; o >>= 1) m = fmaxf(m, __shfl_xor_sync(0xffffffffu, m, o));
    float e0 = (lane < OUTC)      ? __expf(v0 - m) : 0.f;
    float e1 = (lane + 32 < OUTC) ? __expf(v1 - m) : 0.f;
    float sum = e0 + e1;
    #pragma unroll
    for (int o = 16; o; o >>= 1) sum += __shfl_xor_sync(0xffffffffu, sum, o);
    float lg = m + logf(sum);
    if (lane < OUTC)      out[(size_t)w * OUTC + lane]      = v0 - lg;
    if (lane + 32 < OUTC) out[(size_t)w * OUTC + lane + 32] = v1 - lg;
}

// ---------------------------------------------------------------------------
// Launcher: 3 GAT layers, all on the legacy stream (graph-capturable)
// ---------------------------------------------------------------------------
extern "C" void kernel_launch(void* const* d_in, const int* in_sizes, int n_in,
                              void* d_out, int out_size)
{
    const float* x   = (const float*)d_in[0];
    const int*   ei  = (const int*)  d_in[1];
    const int*   srcv = ei;
    const int*   dstv = ei + EE;
    const float* W1  = (const float*)d_in[2];
    const float* as1 = (const float*)d_in[3];
    const float* ad1 = (const float*)d_in[4];
    const float* b1  = (const float*)d_in[5];
    const float* W2  = (const float*)d_in[6];
    const float* as2 = (const float*)d_in[7];
    const float* ad2 = (const float*)d_in[8];
    const float* b2  = (const float*)d_in[9];
    const float* W3  = (const float*)d_in[10];
    const float* as3 = (const float*)d_in[11];
    const float* ad3 = (const float*)d_in[12];
    const float* b3  = (const float*)d_in[13];
    float* out = (float*)d_out;

    dim3 blk(256);
    dim3 gemm_g1((F1 + BN - 1) / BN,   (NN + BM - 1) / BM);
    dim3 gemm_g3((OUTC + BN - 1) / BN, (NN + BM - 1) / BM);
    int nbEdgeH8 = (E2V * 8 + 255) / 256;
    int nbEdgeH1 = (E2V + 255) / 256;
    int nbAgg    = (E2V * 32 + 255) / 256;
    int nbNF     = (NN * F1 + 255) / 256;
    int nbNH     = (NN * 8 + 255) / 256;
    int nbN      = (NN + 255) / 256;
    int nbLsm    = (NN * 32 + 255) / 256;

    // ---- layer 1: in=128 -> 8x32 ----
    sgemm_k<<<gemm_g1, blk>>>(x, W1, NN, F1, 128, 0);
    dots_k<<<nbNH, blk>>>(as1, ad1, NN, 8, 32);
    zero_out_k<<<nbNF, blk>>>(NN * F1);
    edge_max_k<8><<<nbEdgeH8, blk>>>(srcv, dstv);
    edge_sum_k<8><<<nbEdgeH8, blk>>>(srcv, dstv);
    aggregate8_k<<<nbAgg, blk>>>(srcv, dstv);
    bias_relu_k<<<nbNF, blk>>>(b1, NN * F1);

    // ---- layer 2: 256 -> 8x32 ----
    sgemm_k<<<gemm_g1, blk>>>(nullptr, W2, NN, F1, F1, 1);
    dots_k<<<nbNH, blk>>>(as2, ad2, NN, 8, 32);
    zero_out_k<<<nbNF, blk>>>(NN * F1);
    edge_max_k<8><<<nbEdgeH8, blk>>>(srcv, dstv);
    edge_sum_k<8><<<nbEdgeH8, blk>>>(srcv, dstv);
    aggregate8_k<<<nbAgg, blk>>>(srcv, dstv);
    bias_relu_k<<<nbNF, blk>>>(b2, NN * F1);

    // ---- layer 3: 256 -> 40 (1 head) + log_softmax ----
    sgemm_k<<<gemm_g3, blk>>>(nullptr, W3, NN, OUTC, F1, 1);
    dots_k<<<nbN, blk>>>(as3, ad3, NN, 1, OUTC);
    zero_out_k<<<(NN * OUTC + 255) / 256, blk>>>(NN * OUTC);
    edge_max_k<1><<<nbEdgeH1, blk>>>(srcv, dstv);
    edge_sum_k<1><<<nbEdgeH1, blk>>>(srcv, dstv);
    aggregate1_k<<<nbAgg, blk>>>(srcv, dstv);
    logsoftmax_k<<<nbLsm, blk>>>(b3, out);
}

// round 3
// speedup vs baseline: 1.9613x; 1.9613x over previous
#include <cuda_runtime.h>
#include <math.h>

#define NN   50000
#define EE   800000
#define E2V  (EE + NN)
#define F1   256
#define OUTC 40
#define SB   512
#define NBLK ((NN + SB - 1) / SB)

// ---- scratch ----
__device__ float g_h   [(size_t)NN * F1];
__device__ float g_out [(size_t)NN * F1];
__device__ float g_asrc[NN * 8];
__device__ float g_adst[NN * 8];
__device__ float g_e   [(size_t)E2V * 8];   // per-edge e / exp values
__device__ int   g_deg [NN];
__device__ int   g_rows[NN + 1];
__device__ int   g_cur [NN];
__device__ int   g_colsrc[E2V];
__device__ int   g_bsum[NBLK + 1];

// ===========================================================================
// CSR build (dst-grouped): count -> scan -> scatter
// ===========================================================================
__global__ void init_deg_k()
{
    int i = blockIdx.x * blockDim.x + threadIdx.x;
    if (i < NN) g_deg[i] = 1;   // self loop
}

__global__ void count_k(const int* __restrict__ dst)
{
    int e = blockIdx.x * blockDim.x + threadIdx.x;
    if (e < EE) atomicAdd(&g_deg[dst[e]], 1);
}

__global__ void scan1_k()
{
    __shared__ int sh[SB];
    int i = blockIdx.x * SB + threadIdx.x;
    sh[threadIdx.x] = (i < NN) ? g_deg[i] : 0;
    __syncthreads();
    #pragma unroll
    for (int o = 1; o < SB; o <<= 1) {
        int t = (threadIdx.x >= o) ? sh[threadIdx.x - o] : 0;
        __syncthreads();
        sh[threadIdx.x] += t;
        __syncthreads();
    }
    if (i < NN) g_rows[i + 1] = sh[threadIdx.x];
    if (threadIdx.x == SB - 1) g_bsum[blockIdx.x] = sh[SB - 1];
}

__global__ void scan2_k()
{
    if (threadIdx.x == 0) {
        int acc = 0;
        for (int b = 0; b < NBLK; b++) { int t = g_bsum[b]; g_bsum[b] = acc; acc += t; }
    }
}

__global__ void scan3_k()
{
    int i = blockIdx.x * blockDim.x + threadIdx.x;
    if (i >= NN) return;
    int end = g_rows[i + 1] + g_bsum[i / SB];
    g_rows[i + 1] = end;
    g_cur[i] = end - g_deg[i];
    if (i == 0) g_rows[0] = 0;
}

__global__ void scatter_k(const int* __restrict__ src, const int* __restrict__ dst)
{
    int e = blockIdx.x * blockDim.x + threadIdx.x;
    if (e >= E2V) return;
    int s, d;
    if (e < EE) { s = src[e]; d = dst[e]; } else { s = d = e - EE; }
    int pos = atomicAdd(&g_cur[d], 1);
    g_colsrc[pos] = s;
}

// ===========================================================================
// Attention dot products: a_src[n,h], a_dst[n,h]
// ===========================================================================
__global__ void dots_k(const float* __restrict__ att_s, const float* __restrict__ att_d,
                       int N, int H, int C)
{
    int i = blockIdx.x * blockDim.x + threadIdx.x;
    if (i >= N * H) return;
    int n = i / H, hh = i % H;
    const float* hp = g_h + (size_t)n * H * C + hh * C;
    const float* as = att_s + hh * C;
    const float* ad = att_d + hh * C;
    float s = 0.f, d = 0.f;
    for (int c = 0; c < C; c++) {
        float v = hp[c];
        s = fmaf(v, as[c], s);
        d = fmaf(v, ad[c], d);
    }
    g_asrc[i] = s;
    g_adst[i] = d;
}

// ===========================================================================
// Fused per-node softmax + aggregation, 8 heads x 32 ch. Warp per dst node.
// No atomics: accumulate in registers, single store + fused bias(+relu).
// ===========================================================================
__global__ void __launch_bounds__(256) gat_fused8_k(const float* __restrict__ bias, int relu)
{
    int w = (blockIdx.x * blockDim.x + threadIdx.x) >> 5;
    int lane = threadIdx.x & 31;
    if (w >= NN) return;
    int d = w;
    int beg = g_rows[d], end = g_rows[d + 1];

    float adl = (lane < 8) ? g_adst[d * 8 + lane] : 0.f;
    float ad[8];
    #pragma unroll
    for (int h = 0; h < 8; h++) ad[h] = __shfl_sync(0xffffffffu, adl, h);

    // pass 1: e = leaky(asrc[s]+adst[d]), store, per-head max
    float mx[8];
    #pragma unroll
    for (int h = 0; h < 8; h++) mx[h] = -INFINITY;
    for (int p = beg + lane; p < end; p += 32) {
        int s = g_colsrc[p];
        const float4* ap = (const float4*)(g_asrc + s * 8);
        float4 a0 = ap[0], a1 = ap[1];
        float e[8] = {a0.x + ad[0], a0.y + ad[1], a0.z + ad[2], a0.w + ad[3],
                      a1.x + ad[4], a1.y + ad[5], a1.z + ad[6], a1.w + ad[7]};
        #pragma unroll
        for (int h = 0; h < 8; h++) {
            e[h] = e[h] > 0.f ? e[h] : 0.2f * e[h];
            mx[h] = fmaxf(mx[h], e[h]);
        }
        float4* ep = (float4*)(g_e + (size_t)p * 8);
        ep[0] = make_float4(e[0], e[1], e[2], e[3]);
        ep[1] = make_float4(e[4], e[5], e[6], e[7]);
    }
    #pragma unroll
    for (int h = 0; h < 8; h++)
        #pragma unroll
        for (int o = 16; o; o >>= 1)
            mx[h] = fmaxf(mx[h], __shfl_xor_sync(0xffffffffu, mx[h], o));

    // pass 2: exp in place + per-head sum
    float sm[8];
    #pragma unroll
    for (int h = 0; h < 8; h++) sm[h] = 0.f;
    for (int p = beg + lane; p < end; p += 32) {
        float4* ep = (float4*)(g_e + (size_t)p * 8);
        float4 e0 = ep[0], e1 = ep[1];
        float ex[8] = {__expf(e0.x - mx[0]), __expf(e0.y - mx[1]),
                       __expf(e0.z - mx[2]), __expf(e0.w - mx[3]),
                       __expf(e1.x - mx[4]), __expf(e1.y - mx[5]),
                       __expf(e1.z - mx[6]), __expf(e1.w - mx[7])};
        #pragma unroll
        for (int h = 0; h < 8; h++) sm[h] += ex[h];
        ep[0] = make_float4(ex[0], ex[1], ex[2], ex[3]);
        ep[1] = make_float4(ex[4], ex[5], ex[6], ex[7]);
    }
    #pragma unroll
    for (int h = 0; h < 8; h++)
        #pragma unroll
        for (int o = 16; o; o >>= 1)
            sm[h] += __shfl_xor_sync(0xffffffffu, sm[h], o);

    float inv[8];
    #pragma unroll
    for (int h = 0; h < 8; h++) inv[h] = 1.f / (sm[h] + 1e-16f);

    // pass 3: aggregate. Whole warp walks edges; lane owns channel `lane`
    // of each head h (accumulator acc[h]). h[src] loads are 8 coalesced
    // 128B segments; exp values are broadcast float4 loads.
    float acc[8];
    #pragma unroll
    for (int h = 0; h < 8; h++) acc[h] = 0.f;
    for (int p = beg; p < end; p++) {
        int s = g_colsrc[p];
        const float4* ep = (const float4*)(g_e + (size_t)p * 8);
        float4 e0 = ep[0], e1 = ep[1];
        const float* hp = g_h + (size_t)s * F1;
        acc[0] = fmaf(e0.x * inv[0], hp[  0 + lane], acc[0]);
        acc[1] = fmaf(e0.y * inv[1], hp[ 32 + lane], acc[1]);
        acc[2] = fmaf(e0.z * inv[2], hp[ 64 + lane], acc[2]);
        acc[3] = fmaf(e0.w * inv[3], hp[ 96 + lane], acc[3]);
        acc[4] = fmaf(e1.x * inv[4], hp[128 + lane], acc[4]);
        acc[5] = fmaf(e1.y * inv[5], hp[160 + lane], acc[5]);
        acc[6] = fmaf(e1.z * inv[6], hp[192 + lane], acc[6]);
        acc[7] = fmaf(e1.w * inv[7], hp[224 + lane], acc[7]);
    }
    float* op = g_out + (size_t)d * F1;
    #pragma unroll
    for (int h = 0; h < 8; h++) {
        float v = acc[h] + bias[h * 32 + lane];
        if (relu) v = fmaxf(v, 0.f);
        op[h * 32 + lane] = v;
    }
}

// ===========================================================================
// Fused layer-3: 1 head x 40 ch + bias + log_softmax, warp per node
// ===========================================================================
__global__ void __launch_bounds__(256) gat_fused1_k(const float* __restrict__ bias,
                                                    float* __restrict__ out)
{
    int w = (blockIdx.x * blockDim.x + threadIdx.x) >> 5;
    int lane = threadIdx.x & 31;
    if (w >= NN) return;
    int d = w;
    int beg = g_rows[d], end = g_rows[d + 1];
    float add = g_adst[d];

    float mx = -INFINITY;
    for (int p = beg + lane; p < end; p += 32) {
        int s = g_colsrc[p];
        float e = g_asrc[s] + add;
        e = e > 0.f ? e : 0.2f * e;
        g_e[p] = e;
        mx = fmaxf(mx, e);
    }
    #pragma unroll
    for (int o = 16; o; o >>= 1) mx = fmaxf(mx, __shfl_xor_sync(0xffffffffu, mx, o));

    float sm = 0.f;
    for (int p = beg + lane; p < end; p += 32) {
        float ex = __expf(g_e[p] - mx);
        g_e[p] = ex;
        sm += ex;
    }
    #pragma unroll
    for (int o = 16; o; o >>= 1) sm += __shfl_xor_sync(0xffffffffu, sm, o);
    float inv = 1.f / (sm + 1e-16f);

    float a0 = 0.f, a1 = 0.f;
    for (int p = beg; p < end; p++) {
        int s = g_colsrc[p];
        float al = g_e[p] * inv;
        const float* hp = g_h + (size_t)s * OUTC;
        a0 = fmaf(al, hp[lane], a0);
        if (lane < 8) a1 = fmaf(al, hp[lane + 32], a1);
    }

    // bias + log_softmax over the 40 values held by the warp
    float v0 = a0 + bias[lane];
    float v1 = (lane < 8) ? a1 + bias[lane + 32] : -INFINITY;
    float m = fmaxf(v0, v1);
    #pragma unroll
    for (int o = 16; o; o >>= 1) m = fmaxf(m, __shfl_xor_sync(0xffffffffu, m, o));
    float s2 = __expf(v0 - m) + ((lane < 8) ? __expf(v1 - m) : 0.f);
    #pragma unroll
    for (int o = 16; o; o >>= 1) s2 += __shfl_xor_sync(0xffffffffu, s2, o);
    float lg = m + logf(s2);
    out[(size_t)d * OUTC + lane] = v0 - lg;
    if (lane < 8) out[(size_t)d * OUTC + lane + 32] = v1 - lg;
}

// ===========================================================================
// SGEMM (unchanged from R1): C(g_h) = A[M,K] @ B[K,Ncol]
// ===========================================================================
#define BM 128
#define BN 64
#define BK 16
#define TM 8
#define TN 4

__global__ void sgemm_k(const float* __restrict__ Aext, const float* __restrict__ B,
                        int M, int Ncol, int K, int a_internal)
{
    const float* A = a_internal ? g_out : Aext;
    __shared__ float As[BK][BM + 4];
    __shared__ float Bs[BK][BN];
    int bm = blockIdx.y * BM;
    int bn = blockIdx.x * BN;
    int tid = threadIdx.x;
    int tx = tid & 15;
    int ty = tid >> 4;
    float acc[TM][TN];
    #pragma unroll
    for (int i = 0; i < TM; i++)
        #pragma unroll
        for (int j = 0; j < TN; j++) acc[i][j] = 0.f;

    for (int k0 = 0; k0 < K; k0 += BK) {
        #pragma unroll
        for (int i = 0; i < (BM * BK) / 256; i++) {
            int idx = tid + i * 256;
            int r = idx >> 4;
            int c = idx & 15;
            int gr = bm + r;
            As[c][r] = (gr < M) ? A[(size_t)gr * K + k0 + c] : 0.f;
        }
        #pragma unroll
        for (int i = 0; i < (BK * BN) / 256; i++) {
            int idx = tid + i * 256;
            int r = idx >> 6;
            int c = idx & 63;
            int gc = bn + c;
            Bs[r][c] = (gc < Ncol) ? B[(size_t)(k0 + r) * Ncol + gc] : 0.f;
        }
        __syncthreads();
        #pragma unroll
        for (int k = 0; k < BK; k++) {
            float ra[TM], rb[TN];
            #pragma unroll
            for (int i = 0; i < TM; i++) ra[i] = As[k][ty * TM + i];
            #pragma unroll
            for (int j = 0; j < TN; j++) rb[j] = Bs[k][tx * TN + j];
            #pragma unroll
            for (int i = 0; i < TM; i++)
                #pragma unroll
                for (int j = 0; j < TN; j++)
                    acc[i][j] = fmaf(ra[i], rb[j], acc[i][j]);
        }
        __syncthreads();
    }
    #pragma unroll
    for (int i = 0; i < TM; i++) {
        int r = bm + ty * TM + i;
        if (r >= M) continue;
        #pragma unroll
        for (int j = 0; j < TN; j++) {
            int c = bn + tx * TN + j;
            if (c < Ncol) g_h[(size_t)r * Ncol + c] = acc[i][j];
        }
    }
}

// ===========================================================================
// Launcher
// ===========================================================================
extern "C" void kernel_launch(void* const* d_in, const int* in_sizes, int n_in,
                              void* d_out, int out_size)
{
    const float* x    = (const float*)d_in[0];
    const int*   ei   = (const int*)  d_in[1];
    const int*   srcv = ei;
    const int*   dstv = ei + EE;
    const float* W1  = (const float*)d_in[2];
    const float* as1 = (const float*)d_in[3];
    const float* ad1 = (const float*)d_in[4];
    const float* b1  = (const float*)d_in[5];
    const float* W2  = (const float*)d_in[6];
    const float* as2 = (const float*)d_in[7];
    const float* ad2 = (const float*)d_in[8];
    const float* b2  = (const float*)d_in[9];
    const float* W3  = (const float*)d_in[10];
    const float* as3 = (const float*)d_in[11];
    const float* ad3 = (const float*)d_in[12];
    const float* b3  = (const float*)d_in[13];
    float* out = (float*)d_out;

    dim3 blk(256);
    dim3 gemm_g1((F1 + BN - 1) / BN,   (NN + BM - 1) / BM);
    dim3 gemm_g3((OUTC + BN - 1) / BN, (NN + BM - 1) / BM);
    int nbN    = (NN + 255) / 256;
    int nbE    = (EE + 255) / 256;
    int nbE2   = (E2V + 255) / 256;
    int nbNH   = (NN * 8 + 255) / 256;
    int nbWarp = (NN * 32 + 255) / 256;   // warp per node, 8 warps/block

    // ---- CSR build (once per launch) ----
    init_deg_k<<<nbN, blk>>>();
    count_k<<<nbE, blk>>>(dstv);
    scan1_k<<<NBLK, SB>>>();
    scan2_k<<<1, 32>>>();
    scan3_k<<<nbN, blk>>>();
    scatter_k<<<nbE2, blk>>>(srcv, dstv);

    // ---- layer 1: 128 -> 8x32 ----
    sgemm_k<<<gemm_g1, blk>>>(x, W1, NN, F1, 128, 0);
    dots_k<<<nbNH, blk>>>(as1, ad1, NN, 8, 32);
    gat_fused8_k<<<nbWarp, blk>>>(b1, 1);

    // ---- layer 2: 256 -> 8x32 ----
    sgemm_k<<<gemm_g1, blk>>>(nullptr, W2, NN, F1, F1, 1);
    dots_k<<<nbNH, blk>>>(as2, ad2, NN, 8, 32);
    gat_fused8_k<<<nbWarp, blk>>>(b2, 1);

    // ---- layer 3: 256 -> 40 + log_softmax ----
    sgemm_k<<<gemm_g3, blk>>>(nullptr, W3, NN, OUTC, F1, 1);
    dots_k<<<nbN, blk>>>(as3, ad3, NN, 1, OUTC);
    gat_fused1_k<<<nbWarp, blk>>>(b3, out);
}

// round 5
// speedup vs baseline: 2.6146x; 1.3331x over previous
#include <cuda_runtime.h>
#include <math.h>
#include <stdint.h>

#define NN   50000
#define EE   800000
#define E2V  (EE + NN)
#define F1   256
#define OUTC 40
#define SB   512
#define NBLK ((NN + SB - 1) / SB)

// ---- scratch ----
__device__ float g_h   [(size_t)NN * F1];
__device__ float g_out [(size_t)NN * F1];
__device__ float g_asrc[NN * 8];
__device__ float g_adst[NN * 8];
__device__ float g_e   [(size_t)E2V * 8];
__device__ int   g_deg [NN];
__device__ int   g_rows[NN + 1];
__device__ int   g_cur [NN];
__device__ int   g_colsrc[E2V];
__device__ int   g_bsum[NBLK + 1];

// ===========================================================================
// CSR build (dst-grouped): count -> scan -> scatter
// ===========================================================================
__global__ void init_deg_k()
{
    int i = blockIdx.x * blockDim.x + threadIdx.x;
    if (i < NN) g_deg[i] = 1;
}

__global__ void count_k(const int* __restrict__ dst)
{
    int e = blockIdx.x * blockDim.x + threadIdx.x;
    if (e < EE) atomicAdd(&g_deg[dst[e]], 1);
}

__global__ void scan1_k()
{
    __shared__ int sh[SB];
    int i = blockIdx.x * SB + threadIdx.x;
    sh[threadIdx.x] = (i < NN) ? g_deg[i] : 0;
    __syncthreads();
    #pragma unroll
    for (int o = 1; o < SB; o <<= 1) {
        int t = (threadIdx.x >= o) ? sh[threadIdx.x - o] : 0;
        __syncthreads();
        sh[threadIdx.x] += t;
        __syncthreads();
    }
    if (i < NN) g_rows[i + 1] = sh[threadIdx.x];
    if (threadIdx.x == SB - 1) g_bsum[blockIdx.x] = sh[SB - 1];
}

__global__ void scan2_k()
{
    __shared__ int sh[128];
    int t = threadIdx.x;
    int v = (t < NBLK) ? g_bsum[t] : 0;
    sh[t] = v;
    __syncthreads();
    #pragma unroll
    for (int o = 1; o < 128; o <<= 1) {
        int u = (t >= o) ? sh[t - o] : 0;
        __syncthreads();
        sh[t] += u;
        __syncthreads();
    }
    if (t < NBLK) g_bsum[t] = sh[t] - v;   // exclusive
}

__global__ void scan3_k()
{
    int i = blockIdx.x * blockDim.x + threadIdx.x;
    if (i >= NN) return;
    int end = g_rows[i + 1] + g_bsum[i / SB];
    g_rows[i + 1] = end;
    g_cur[i] = end - g_deg[i];
    if (i == 0) g_rows[0] = 0;
}

__global__ void scatter_k(const int* __restrict__ src, const int* __restrict__ dst)
{
    int e = blockIdx.x * blockDim.x + threadIdx.x;
    if (e >= E2V) return;
    int s, d;
    if (e < EE) { s = src[e]; d = dst[e]; } else { s = d = e - EE; }
    int pos = atomicAdd(&g_cur[d], 1);
    g_colsrc[pos] = s;
}

// ===========================================================================
// Attention dot products
// ===========================================================================
__global__ void dots_k(const float* __restrict__ att_s, const float* __restrict__ att_d,
                       int N, int H, int C)
{
    int i = blockIdx.x * blockDim.x + threadIdx.x;
    if (i >= N * H) return;
    int n = i / H, hh = i % H;
    const float* hp = g_h + (size_t)n * H * C + hh * C;
    const float* as = att_s + hh * C;
    const float* ad = att_d + hh * C;
    float s = 0.f, d = 0.f;
    for (int c = 0; c < C; c++) {
        float v = hp[c];
        s = fmaf(v, as[c], s);
        d = fmaf(v, ad[c], d);
    }
    g_asrc[i] = s;
    g_adst[i] = d;
}

// ===========================================================================
// Fused per-node softmax + aggregation, 8 heads x 32 ch. Warp per dst node.
// ===========================================================================
__global__ void __launch_bounds__(256) gat_fused8_k(const float* __restrict__ bias, int relu)
{
    int w = (blockIdx.x * blockDim.x + threadIdx.x) >> 5;
    int lane = threadIdx.x & 31;
    if (w >= NN) return;
    int d = w;
    int beg = g_rows[d], end = g_rows[d + 1];

    float adl = (lane < 8) ? g_adst[d * 8 + lane] : 0.f;
    float ad[8];
    #pragma unroll
    for (int h = 0; h < 8; h++) ad[h] = __shfl_sync(0xffffffffu, adl, h);

    float mx[8];
    #pragma unroll
    for (int h = 0; h < 8; h++) mx[h] = -INFINITY;
    for (int p = beg + lane; p < end; p += 32) {
        int s = g_colsrc[p];
        const float4* ap = (const float4*)(g_asrc + s * 8);
        float4 a0 = ap[0], a1 = ap[1];
        float e[8] = {a0.x + ad[0], a0.y + ad[1], a0.z + ad[2], a0.w + ad[3],
                      a1.x + ad[4], a1.y + ad[5], a1.z + ad[6], a1.w + ad[7]};
        #pragma unroll
        for (int h = 0; h < 8; h++) {
            e[h] = e[h] > 0.f ? e[h] : 0.2f * e[h];
            mx[h] = fmaxf(mx[h], e[h]);
        }
        float4* ep = (float4*)(g_e + (size_t)p * 8);
        ep[0] = make_float4(e[0], e[1], e[2], e[3]);
        ep[1] = make_float4(e[4], e[5], e[6], e[7]);
    }
    #pragma unroll
    for (int h = 0; h < 8; h++)
        #pragma unroll
        for (int o = 16; o; o >>= 1)
            mx[h] = fmaxf(mx[h], __shfl_xor_sync(0xffffffffu, mx[h], o));

    float sm[8];
    #pragma unroll
    for (int h = 0; h < 8; h++) sm[h] = 0.f;
    for (int p = beg + lane; p < end; p += 32) {
        float4* ep = (float4*)(g_e + (size_t)p * 8);
        float4 e0 = ep[0], e1 = ep[1];
        float ex[8] = {__expf(e0.x - mx[0]), __expf(e0.y - mx[1]),
                       __expf(e0.z - mx[2]), __expf(e0.w - mx[3]),
                       __expf(e1.x - mx[4]), __expf(e1.y - mx[5]),
                       __expf(e1.z - mx[6]), __expf(e1.w - mx[7])};
        #pragma unroll
        for (int h = 0; h < 8; h++) sm[h] += ex[h];
        ep[0] = make_float4(ex[0], ex[1], ex[2], ex[3]);
        ep[1] = make_float4(ex[4], ex[5], ex[6], ex[7]);
    }
    #pragma unroll
    for (int h = 0; h < 8; h++)
        #pragma unroll
        for (int o = 16; o; o >>= 1)
            sm[h] += __shfl_xor_sync(0xffffffffu, sm[h], o);

    float inv[8];
    #pragma unroll
    for (int h = 0; h < 8; h++) inv[h] = 1.f / (sm[h] + 1e-16f);

    float acc[8];
    #pragma unroll
    for (int h = 0; h < 8; h++) acc[h] = 0.f;
    for (int p = beg; p < end; p++) {
        int s = g_colsrc[p];
        const float4* ep = (const float4*)(g_e + (size_t)p * 8);
        float4 e0 = ep[0], e1 = ep[1];
        const float* hp = g_h + (size_t)s * F1;
        acc[0] = fmaf(e0.x * inv[0], hp[  0 + lane], acc[0]);
        acc[1] = fmaf(e0.y * inv[1], hp[ 32 + lane], acc[1]);
        acc[2] = fmaf(e0.z * inv[2], hp[ 64 + lane], acc[2]);
        acc[3] = fmaf(e0.w * inv[3], hp[ 96 + lane], acc[3]);
        acc[4] = fmaf(e1.x * inv[4], hp[128 + lane], acc[4]);
        acc[5] = fmaf(e1.y * inv[5], hp[160 + lane], acc[5]);
        acc[6] = fmaf(e1.z * inv[6], hp[192 + lane], acc[6]);
        acc[7] = fmaf(e1.w * inv[7], hp[224 + lane], acc[7]);
    }
    float* op = g_out + (size_t)d * F1;
    #pragma unroll
    for (int h = 0; h < 8; h++) {
        float v = acc[h] + bias[h * 32 + lane];
        if (relu) v = fmaxf(v, 0.f);
        op[h * 32 + lane] = v;
    }
}

// ===========================================================================
// Fused layer-3: 1 head x 40 ch + bias + log_softmax, warp per node
// ===========================================================================
__global__ void __launch_bounds__(256) gat_fused1_k(const float* __restrict__ bias,
                                                    float* __restrict__ out)
{
    int w = (blockIdx.x * blockDim.x + threadIdx.x) >> 5;
    int lane = threadIdx.x & 31;
    if (w >= NN) return;
    int d = w;
    int beg = g_rows[d], end = g_rows[d + 1];
    float add = g_adst[d];

    float mx = -INFINITY;
    for (int p = beg + lane; p < end; p += 32) {
        int s = g_colsrc[p];
        float e = g_asrc[s] + add;
        e = e > 0.f ? e : 0.2f * e;
        g_e[p] = e;
        mx = fmaxf(mx, e);
    }
    #pragma unroll
    for (int o = 16; o; o >>= 1) mx = fmaxf(mx, __shfl_xor_sync(0xffffffffu, mx, o));

    float sm = 0.f;
    for (int p = beg + lane; p < end; p += 32) {
        float ex = __expf(g_e[p] - mx);
        g_e[p] = ex;
        sm += ex;
    }
    #pragma unroll
    for (int o = 16; o; o >>= 1) sm += __shfl_xor_sync(0xffffffffu, sm, o);
    float inv = 1.f / (sm + 1e-16f);

    float a0 = 0.f, a1 = 0.f;
    for (int p = beg; p < end; p++) {
        int s = g_colsrc[p];
        float al = g_e[p] * inv;
        const float* hp = g_h + (size_t)s * OUTC;
        a0 = fmaf(al, hp[lane], a0);
        if (lane < 8) a1 = fmaf(al, hp[lane + 32], a1);
    }

    float v0 = a0 + bias[lane];
    float v1 = (lane < 8) ? a1 + bias[lane + 32] : -INFINITY;
    float m = fmaxf(v0, v1);
    #pragma unroll
    for (int o = 16; o; o >>= 1) m = fmaxf(m, __shfl_xor_sync(0xffffffffu, m, o));
    float s2 = __expf(v0 - m) + ((lane < 8) ? __expf(v1 - m) : 0.f);
    #pragma unroll
    for (int o = 16; o; o >>= 1) s2 += __shfl_xor_sync(0xffffffffu, s2, o);
    float lg = m + logf(s2);
    out[(size_t)d * OUTC + lane] = v0 - lg;
    if (lane < 8) out[(size_t)d * OUTC + lane + 32] = v1 - lg;
}

// ===========================================================================
// TF32 tensor-core GEMM: g_h = A[M,K] @ B[K,Ncol]
// 128x64x16 block, 8 warps (4x2), warp tile 32x32, mma m16n8k8 tf32
// ===========================================================================
#define GBM 128
#define GBN 64
#define GBK 16
#define AS_STRIDE 20   // 16 + 4 pad
#define BS_STRIDE 72   // 64 + 8 pad

__device__ __forceinline__ uint32_t to_tf32(float x)
{
    uint32_t r;
    asm("cvt.rna.tf32.f32 %0, %1;" : "=r"(r) : "f"(x));
    return r;
}

__device__ __forceinline__ void mma1688(float* c, const uint32_t* a, const uint32_t* b)
{
    asm volatile(
        "mma.sync.aligned.m16n8k8.row.col.f32.tf32.tf32.f32 "
        "{%0,%1,%2,%3},{%4,%5,%6,%7},{%8,%9},{%0,%1,%2,%3};"
        : "+f"(c[0]), "+f"(c[1]), "+f"(c[2]), "+f"(c[3])
        : "r"(a[0]), "r"(a[1]), "r"(a[2]), "r"(a[3]), "r"(b[0]), "r"(b[1]));
}

__global__ void __launch_bounds__(256) tf32gemm_k(const float* __restrict__ Aext,
                                                  const float* __restrict__ B,
                                                  int M, int Ncol, int K, int a_internal)
{
    const float* A = a_internal ? g_out : Aext;
    __shared__ uint32_t As[GBM * AS_STRIDE];
    __shared__ uint32_t Bs[GBK * BS_STRIDE];

    int tid  = threadIdx.x;
    int warp = tid >> 5;
    int lane = tid & 31;
    int wm = warp >> 1;          // 0..3
    int wn = warp & 1;           // 0..1
    int bm = blockIdx.y * GBM;
    int bn = blockIdx.x * GBN;
    int lr = lane >> 2;          // 0..7
    int lc = lane & 3;           // 0..3

    float c[2][4][4];
    #pragma unroll
    for (int i = 0; i < 2; i++)
        #pragma unroll
        for (int j = 0; j < 4; j++)
            #pragma unroll
            for (int r = 0; r < 4; r++) c[i][j][r] = 0.f;

    for (int k0 = 0; k0 < K; k0 += GBK) {
        // load A tile: 128x16 = 512 float4, 2 per thread
        #pragma unroll
        for (int i = 0; i < 2; i++) {
            int idx = tid + i * 256;
            int r   = idx >> 2;
            int c4  = (idx & 3) * 4;
            int gr  = bm + r;
            float4 v = make_float4(0.f, 0.f, 0.f, 0.f);
            if (gr < M) v = *(const float4*)(A + (size_t)gr * K + k0 + c4);
            uint32_t* dst = As + r * AS_STRIDE + c4;
            dst[0] = to_tf32(v.x); dst[1] = to_tf32(v.y);
            dst[2] = to_tf32(v.z); dst[3] = to_tf32(v.w);
        }
        // load B tile: 16x64 = 256 float4, 1 per thread
        {
            int r  = tid >> 4;
            int c4 = (tid & 15) * 4;
            int gc = bn + c4;
            float4 v = make_float4(0.f, 0.f, 0.f, 0.f);
            if (gc < Ncol) v = *(const float4*)(B + (size_t)(k0 + r) * Ncol + gc);
            uint32_t* dst = Bs + r * BS_STRIDE + c4;
            dst[0] = to_tf32(v.x); dst[1] = to_tf32(v.y);
            dst[2] = to_tf32(v.z); dst[3] = to_tf32(v.w);
        }
        __syncthreads();

        #pragma unroll
        for (int kk = 0; kk < GBK; kk += 8) {
            uint32_t afrag[2][4], bfrag[4][2];
            #pragma unroll
            for (int i = 0; i < 2; i++) {
                int rb = wm * 32 + i * 16;
                afrag[i][0] = As[(rb + lr)     * AS_STRIDE + kk + lc];
                afrag[i][1] = As[(rb + 8 + lr) * AS_STRIDE + kk + lc];
                afrag[i][2] = As[(rb + lr)     * AS_STRIDE + kk + 4 + lc];
                afrag[i][3] = As[(rb + 8 + lr) * AS_STRIDE + kk + 4 + lc];
            }
            #pragma unroll
            for (int j = 0; j < 4; j++) {
                int nb = wn * 32 + j * 8;
                bfrag[j][0] = Bs[(kk + lc)     * BS_STRIDE + nb + lr];
                bfrag[j][1] = Bs[(kk + 4 + lc) * BS_STRIDE + nb + lr];
            }
            #pragma unroll
            for (int i = 0; i < 2; i++)
                #pragma unroll
                for (int j = 0; j < 4; j++)
                    mma1688(c[i][j], afrag[i], bfrag[j]);
        }
        __syncthreads();
    }

    // epilogue: c0/c1 -> row lr, cols 2*lc, 2*lc+1; c2/c3 -> row lr+8
    #pragma unroll
    for (int i = 0; i < 2; i++) {
        int r0 = bm + wm * 32 + i * 16 + lr;
        #pragma unroll
        for (int j = 0; j < 4; j++) {
            int col = bn + wn * 32 + j * 8 + lc * 2;
            if (col < Ncol) {
                if (r0 < M) {
                    g_h[(size_t)r0 * Ncol + col]     = c[i][j][0];
                    g_h[(size_t)r0 * Ncol + col + 1] = c[i][j][1];
                }
                if (r0 + 8 < M) {
                    g_h[(size_t)(r0 + 8) * Ncol + col]     = c[i][j][2];
                    g_h[(size_t)(r0 + 8) * Ncol + col + 1] = c[i][j][3];
                }
            }
        }
    }
}

// ===========================================================================
// Launcher
// ===========================================================================
extern "C" void kernel_launch(void* const* d_in, const int* in_sizes, int n_in,
                              void* d_out, int out_size)
{
    const float* x    = (const float*)d_in[0];
    const int*   ei   = (const int*)  d_in[1];
    const int*   srcv = ei;
    const int*   dstv = ei + EE;
    const float* W1  = (const float*)d_in[2];
    const float* as1 = (const float*)d_in[3];
    const float* ad1 = (const float*)d_in[4];
    const float* b1  = (const float*)d_in[5];
    const float* W2  = (const float*)d_in[6];
    const float* as2 = (const float*)d_in[7];
    const float* ad2 = (const float*)d_in[8];
    const float* b2  = (const float*)d_in[9];
    const float* W3  = (const float*)d_in[10];
    const float* as3 = (const float*)d_in[11];
    const float* ad3 = (const float*)d_in[12];
    const float* b3  = (const float*)d_in[13];
    float* out = (float*)d_out;

    dim3 blk(256);
    dim3 gemm_g1((F1 + GBN - 1) / GBN,   (NN + GBM - 1) / GBM);
    dim3 gemm_g3((OUTC + GBN - 1) / GBN, (NN + GBM - 1) / GBM);
    int nbN    = (NN + 255) / 256;
    int nbE    = (EE + 255) / 256;
    int nbE2   = (E2V + 255) / 256;
    int nbNH   = (NN * 8 + 255) / 256;
    int nbWarp = (NN * 32 + 255) / 256;

    // ---- CSR build ----
    init_deg_k<<<nbN, blk>>>();
    count_k<<<nbE, blk>>>(dstv);
    scan1_k<<<NBLK, SB>>>();
    scan2_k<<<1, 128>>>();
    scan3_k<<<nbN, blk>>>();
    scatter_k<<<nbE2, blk>>>(srcv, dstv);

    // ---- layer 1: 128 -> 8x32 ----
    tf32gemm_k<<<gemm_g1, blk>>>(x, W1, NN, F1, 128, 0);
    dots_k<<<nbNH, blk>>>(as1, ad1, NN, 8, 32);
    gat_fused8_k<<<nbWarp, blk>>>(b1, 1);

    // ---- layer 2: 256 -> 8x32 ----
    tf32gemm_k<<<gemm_g1, blk>>>(nullptr, W2, NN, F1, F1, 1);
    dots_k<<<nbNH, blk>>>(as2, ad2, NN, 8, 32);
    gat_fused8_k<<<nbWarp, blk>>>(b2, 1);

    // ---- layer 3: 256 -> 40 + log_softmax ----
    tf32gemm_k<<<gemm_g3, blk>>>(nullptr, W3, NN, OUTC, F1, 1);
    dots_k<<<nbN, blk>>>(as3, ad3, NN, 1, OUTC);
    gat_fused1_k<<<nbWarp, blk>>>(b3, out);
}